// round 11
// baseline (speedup 1.0000x reference)
#include <cuda_runtime.h>

// Scratch: __device__ globals only (no allocation allowed).
#define MAXV (1 << 19)      // 512k vertices (actual V ~ 185k)
#define KMAX 16             // adjacency storage slots per vertex
#define KUNROLL 8           // fast path covers valence <= 8

// Windowed-gather geometry (small halo: catches Δz/Δy neighbors;
// far Δx neighbors fall back to __ldg).
#define VPB  512            // vertices per gather block
#define TG   256            // threads per gather block (2 verts/thread)
#define HALO 256            // window halo each side (index units)
#define WIN  (VPB + 2 * HALO)   // 1024 float4 = 16 KB smem -> 8 blocks/SM

__device__ float4 g_x[MAXV];            // positions (iter-1 input)
__device__ float4 g_y[MAXV];            // positions after iter 1
__device__ int    g_cnt[MAXV];          // degree / slot counter
__device__ int    g_adj[KMAX * MAXV];   // slot-major adjacency (coalesced over v)

// ---------------------------------------------------------------------------
// Fused: pack v -> g_x + zero counters (first gV blocks); faces int->float
// copy (remaining blocks, int4-vectorized).
__global__ void k_repack_faces(const float* __restrict__ v, int V, int gV,
                               const int* __restrict__ faces,
                               float* __restrict__ fout, int nF3) {
    if ((int)blockIdx.x < gV) {
        int i = blockIdx.x * blockDim.x + threadIdx.x;
        if (i < V) {
            g_x[i] = make_float4(v[3 * i], v[3 * i + 1], v[3 * i + 2], 0.f);
            g_cnt[i] = 0;
        }
    } else {
        int t = (blockIdx.x - gV) * blockDim.x + threadIdx.x;
        int base = t * 4;
        if (base + 4 <= nF3) {
            int4 f = *(const int4*)(faces + base);
            *(float4*)(fout + base) =
                make_float4((float)f.x, (float)f.y, (float)f.z, (float)f.w);
        } else if (base < nF3) {
            for (int j = base; j < nF3; ++j) fout[j] = (float)faces[j];
        }
    }
}

// Build adjacency: each edge registers itself at both endpoints.
__global__ void k_fill(const int2* __restrict__ edges, int E) {
    int i = blockIdx.x * blockDim.x + threadIdx.x;
    if (i < E) {
        int2 e = edges[i];
        int sa = atomicAdd(&g_cnt[e.x], 1) & (KMAX - 1);
        int sb = atomicAdd(&g_cnt[e.y], 1) & (KMAX - 1);
        g_adj[sa * MAXV + e.x] = e.y;
        g_adj[sb * MAXV + e.y] = e.x;
    }
}

// Small-halo windowed gather: near neighbors (Δ index within ±HALO-ish) hit
// the smem window; far neighbors (the ~2 Δx ones) use __ldg. Correctness is
// independent of the locality assumption (fallback always valid).
template <bool FINAL>
__global__ __launch_bounds__(TG) void k_gather_win(float* __restrict__ out, int V) {
    __shared__ float4 win[WIN];
    const float4* __restrict__ src = FINAL ? g_y : g_x;

    const int base  = (int)blockIdx.x * VPB;
    const int wbase = base - HALO;

    // Stage window (clamped at ends; clamped entries harmless).
#pragma unroll
    for (int r = 0; r < WIN / TG; ++r) {
        int i = r * TG + threadIdx.x;
        int idx = wbase + i;
        idx = idx < 0 ? 0 : (idx >= V ? V - 1 : idx);
        win[i] = src[idx];
    }
    __syncthreads();

#pragma unroll
    for (int r = 0; r < VPB / TG; ++r) {
        int v = base + r * TG + threadIdx.x;
        if (v >= V) continue;
        int d = g_cnt[v];
        if (d > KMAX) d = KMAX;

        // Coalesced adjacency (slot-major), unconditional front batch.
        int nb[KUNROLL];
#pragma unroll
        for (int j = 0; j < KUNROLL; ++j)
            nb[j] = g_adj[j * MAXV + v];

        float sx = 0.f, sy = 0.f, sz = 0.f;
#pragma unroll
        for (int j = 0; j < KUNROLL; ++j) {
            if (j < d) {
                int rel = nb[j] - wbase;
                float4 p = ((unsigned)rel < (unsigned)WIN) ? win[rel]
                                                           : __ldg(&src[nb[j]]);
                sx += p.x; sy += p.y; sz += p.z;
            }
        }
        for (int j = KUNROLL; j < d; ++j) {
            float4 p = __ldg(&src[g_adj[j * MAXV + v]]);
            sx += p.x; sy += p.y; sz += p.z;
        }

        float inv = 1.0f / fmaxf((float)d, 1.0f);
        if (FINAL) {
            out[3 * v + 0] = sx * inv;
            out[3 * v + 1] = sy * inv;
            out[3 * v + 2] = sz * inv;
        } else {
            g_y[v] = make_float4(sx * inv, sy * inv, sz * inv, 0.f);
        }
    }
}

// ---------------------------------------------------------------------------
extern "C" void kernel_launch(void* const* d_in, const int* in_sizes, int n_in,
                              void* d_out, int out_size) {
    const float* v     = (const float*)d_in[0];   // [1,V,3] f32
    const int2*  edges = (const int2*)d_in[1];    // [E,2]   i32
    const int*   faces = (const int*)d_in[2];     // [1,F,3] i32

    const int V   = in_sizes[0] / 3;
    const int E   = in_sizes[1] / 2;
    const int nF3 = in_sizes[2];

    float* out  = (float*)d_out;
    float* fout = out + 3 * V;
    const bool do_faces = (out_size >= 3 * V + nF3);

    const int T = 256;
    const int gV = (V + T - 1) / T;
    const int gE = (E + T - 1) / T;
    const int gF = do_faces ? ((nF3 + 4 * T - 1) / (4 * T)) : 0;
    const int gW = (V + VPB - 1) / VPB;

    k_repack_faces<<<gV + gF, T>>>(v, V, gV, faces, fout, do_faces ? nF3 : 0);
    k_fill<<<gE, T>>>(edges, E);
    k_gather_win<false><<<gW, TG>>>(nullptr, V);   // iter 1: g_x -> g_y
    k_gather_win<true><<<gW, TG>>>(out, V);        // iter 2: g_y -> out
}

// round 16
// speedup vs baseline: 1.1780x; 1.1780x over previous
#include <cuda_runtime.h>

// Scratch: __device__ globals only (no allocation allowed).
#define MAXV (1 << 19)      // 512k vertices (actual V ~ 185k)
#define KMAX 16             // adjacency storage slots per vertex
#define KUNROLL 8           // fast path covers valence <= 8
#define PADKEY 0x7fffffff

__device__ float4 g_x[MAXV];            // positions (iter-1 input)
__device__ float4 g_y[MAXV];            // positions after iter 1
__device__ int    g_cnt[MAXV];          // degree / slot counter
__device__ int    g_adj[KMAX * MAXV];   // slot-major adjacency (coalesced over v)

// ---------------------------------------------------------------------------
// Fused: pack v -> g_x + zero counters (first gV blocks); faces int->float
// copy (remaining blocks, int4-vectorized).
__global__ void k_repack_faces(const float* __restrict__ v, int V, int gV,
                               const int* __restrict__ faces,
                               float* __restrict__ fout, int nF3) {
    if ((int)blockIdx.x < gV) {
        int i = blockIdx.x * blockDim.x + threadIdx.x;
        if (i < V) {
            g_x[i] = make_float4(v[3 * i], v[3 * i + 1], v[3 * i + 2], 0.f);
            g_cnt[i] = 0;
        }
    } else {
        int t = (blockIdx.x - gV) * blockDim.x + threadIdx.x;
        int base = t * 4;
        if (base + 4 <= nF3) {
            int4 f = *(const int4*)(faces + base);
            *(float4*)(fout + base) =
                make_float4((float)f.x, (float)f.y, (float)f.z, (float)f.w);
        } else if (base < nF3) {
            for (int j = base; j < nF3; ++j) fout[j] = (float)faces[j];
        }
    }
}

// Build adjacency: each edge registers itself at both endpoints.
__global__ void k_fill(const int2* __restrict__ edges, int E) {
    int i = blockIdx.x * blockDim.x + threadIdx.x;
    if (i < E) {
        int2 e = edges[i];
        int sa = atomicAdd(&g_cnt[e.x], 1) & (KMAX - 1);
        int sb = atomicAdd(&g_cnt[e.y], 1) & (KMAX - 1);
        g_adj[sa * MAXV + e.x] = e.y;
        g_adj[sb * MAXV + e.y] = e.x;
    }
}

// Sort each vertex's first 8 adjacency slots ascending (registers, 19-comp
// odd-even merge network). Makes slot-j neighbor indices monotone in v, so
// the gather's slot-j warp load hits consecutive-ish lines -> coalescing.
#define CSWAP(a, b) { int lo = min(a, b), hi = max(a, b); a = lo; b = hi; }
__global__ void k_sortadj(int V) {
    int v = blockIdx.x * blockDim.x + threadIdx.x;
    if (v >= V) return;
    int d = g_cnt[v];
    int e0 = (d > 0) ? g_adj[0 * MAXV + v] : PADKEY;
    int e1 = (d > 1) ? g_adj[1 * MAXV + v] : PADKEY;
    int e2 = (d > 2) ? g_adj[2 * MAXV + v] : PADKEY;
    int e3 = (d > 3) ? g_adj[3 * MAXV + v] : PADKEY;
    int e4 = (d > 4) ? g_adj[4 * MAXV + v] : PADKEY;
    int e5 = (d > 5) ? g_adj[5 * MAXV + v] : PADKEY;
    int e6 = (d > 6) ? g_adj[6 * MAXV + v] : PADKEY;
    int e7 = (d > 7) ? g_adj[7 * MAXV + v] : PADKEY;
    CSWAP(e0, e1); CSWAP(e2, e3); CSWAP(e4, e5); CSWAP(e6, e7);
    CSWAP(e0, e2); CSWAP(e1, e3); CSWAP(e4, e6); CSWAP(e5, e7);
    CSWAP(e1, e2); CSWAP(e5, e6);
    CSWAP(e0, e4); CSWAP(e1, e5); CSWAP(e2, e6); CSWAP(e3, e7);
    CSWAP(e2, e4); CSWAP(e3, e5);
    CSWAP(e1, e2); CSWAP(e3, e4); CSWAP(e5, e6);
    g_adj[0 * MAXV + v] = e0;
    g_adj[1 * MAXV + v] = e1;
    g_adj[2 * MAXV + v] = e2;
    g_adj[3 * MAXV + v] = e3;
    g_adj[4 * MAXV + v] = e4;
    g_adj[5 * MAXV + v] = e5;
    g_adj[6 * MAXV + v] = e6;
    g_adj[7 * MAXV + v] = e7;
}

// Gather (R4 shape): coalesced adjacency front batch + predicated random
// position loads. With sorted slots, the random loads coalesce across lanes.
template <bool FINAL>
__global__ void k_gather(float* __restrict__ out, int V) {
    int v = blockIdx.x * blockDim.x + threadIdx.x;
    if (v >= V) return;
    int d = g_cnt[v];
    if (d > KMAX) d = KMAX;
    const float4* __restrict__ src = FINAL ? g_y : g_x;

    int nb[KUNROLL];
#pragma unroll
    for (int j = 0; j < KUNROLL; ++j)
        nb[j] = g_adj[j * MAXV + v];

    float sx = 0.f, sy = 0.f, sz = 0.f;
#pragma unroll
    for (int j = 0; j < KUNROLL; ++j) {
        if (j < d) {
            float4 p = __ldg(&src[nb[j]]);
            sx += p.x; sy += p.y; sz += p.z;
        }
    }
    for (int j = KUNROLL; j < d; ++j) {
        float4 p = __ldg(&src[g_adj[j * MAXV + v]]);
        sx += p.x; sy += p.y; sz += p.z;
    }

    float inv = 1.0f / fmaxf((float)d, 1.0f);
    if (FINAL) {
        out[3 * v + 0] = sx * inv;
        out[3 * v + 1] = sy * inv;
        out[3 * v + 2] = sz * inv;
    } else {
        g_y[v] = make_float4(sx * inv, sy * inv, sz * inv, 0.f);
    }
}

// ---------------------------------------------------------------------------
extern "C" void kernel_launch(void* const* d_in, const int* in_sizes, int n_in,
                              void* d_out, int out_size) {
    const float* v     = (const float*)d_in[0];   // [1,V,3] f32
    const int2*  edges = (const int2*)d_in[1];    // [E,2]   i32
    const int*   faces = (const int*)d_in[2];     // [1,F,3] i32

    const int V   = in_sizes[0] / 3;
    const int E   = in_sizes[1] / 2;
    const int nF3 = in_sizes[2];

    float* out  = (float*)d_out;
    float* fout = out + 3 * V;
    const bool do_faces = (out_size >= 3 * V + nF3);

    const int T = 256;
    const int gV = (V + T - 1) / T;
    const int gE = (E + T - 1) / T;
    const int gF = do_faces ? ((nF3 + 4 * T - 1) / (4 * T)) : 0;

    k_repack_faces<<<gV + gF, T>>>(v, V, gV, faces, fout, do_faces ? nF3 : 0);
    k_fill<<<gE, T>>>(edges, E);
    k_sortadj<<<gV, T>>>(V);
    k_gather<false><<<gV, T>>>(nullptr, V);   // iter 1: g_x -> g_y
    k_gather<true><<<gV, T>>>(out, V);        // iter 2: g_y -> out
}